// round 6
// baseline (speedup 1.0000x reference)
#include <cuda_runtime.h>
#include <cuda_bf16.h>
#include <cstddef>

// ---------------------------------------------------------------------------
// GIN 2-layer forward:
//   agg0 = segsum(x[src] -> dst); h0 = x + agg0
//   t1 = relu(h0 @ W1a + b1a); h = relu(t1 @ W2a + b2a)
//   agg1 = segsum(h[src] -> dst); g0 = h + agg1
//   t2 = relu(g0 @ W1b + b1b); out = t2 @ W2b + b2b
// ---------------------------------------------------------------------------

#define NMAX 50048
#define EMAX 600064

__device__ __align__(256) int   g_off[NMAX + 1];
__device__ __align__(256) int   g_cursor[NMAX];
__device__ __align__(256) int   g_csr[EMAX];
__device__ __align__(256) int   g_bsums[256];
__device__ int   g_is64;
__device__ __align__(256) float g_h0[(size_t)NMAX * 128];
__device__ __align__(256) float g_bufA[(size_t)NMAX * 256];
__device__ __align__(256) float g_bufB[(size_t)NMAX * 256];

// ------------------------- packed f32x2 helpers ----------------------------
__device__ __forceinline__ unsigned long long pack2(float lo, float hi) {
    unsigned long long r;
    asm("mov.b64 %0, {%1, %2};" : "=l"(r) : "f"(lo), "f"(hi));
    return r;
}
__device__ __forceinline__ void fma2(unsigned long long &d, unsigned long long a,
                                     unsigned long long b) {
    asm("fma.rn.f32x2 %0, %1, %2, %3;" : "=l"(d) : "l"(a), "l"(b), "l"(d));
}
__device__ __forceinline__ float2 unpack2(unsigned long long v) {
    float2 r;
    asm("mov.b64 {%0, %1}, %2;" : "=f"(r.x), "=f"(r.y) : "l"(v));
    return r;
}

// ----------------------- edge-index dtype detection ------------------------
// Reads only the first 512 bytes (safe under both int32 and int64 layouts).
// int64 node ids lie in [0, N); int32 pairs misread as int64 are >= 2^32
// unless the high word is 0 (prob ~1/N per element) -> 64 checks decide it.
__global__ void detect_dtype(const long long *__restrict__ ei, int N, int *flag) {
    if (threadIdx.x == 0 && blockIdx.x == 0) {
        int ok = 1;
        for (int i = 0; i < 64; i++) {
            long long v = ei[i];
            if (v < 0 || v >= (long long)N) { ok = 0; break; }
        }
        *flag = ok;
    }
}

__device__ __forceinline__ int edge_at(const void *ei, size_t idx, int is64) {
    if (is64) return (int)((const long long *)ei)[idx];
    return ((const int *)ei)[idx];
}

// ----------------------------- CSR build -----------------------------------
__global__ void zero_counts(int *off, int *cursor, int n) {
    int i = blockIdx.x * blockDim.x + threadIdx.x;
    if (i <= n) off[i] = 0;
    if (i < n) cursor[i] = 0;
}

__global__ void hist_kernel(const void *__restrict__ ei, int E,
                            int *__restrict__ deg, int N) {
    int e = blockIdx.x * blockDim.x + threadIdx.x;
    if (e < E) {
        int dst = edge_at(ei, (size_t)E + e, g_is64);
        if ((unsigned)dst < (unsigned)N) atomicAdd(&deg[dst], 1);
    }
}

// exclusive scan, 512 elems / block
__global__ void scan_block(int *__restrict__ data, int *__restrict__ bsums, int n) {
    __shared__ int sh[512];
    int tid = threadIdx.x;
    int gid = blockIdx.x * 512 + tid;
    int v = (gid < n) ? data[gid] : 0;
    sh[tid] = v;
    __syncthreads();
#pragma unroll
    for (int ofs = 1; ofs < 512; ofs <<= 1) {
        int t = 0;
        if (tid >= ofs) t = sh[tid - ofs];
        __syncthreads();
        sh[tid] += t;
        __syncthreads();
    }
    if (gid < n) data[gid] = sh[tid] - v;   // exclusive
    if (tid == 511) bsums[blockIdx.x] = sh[511];
}

__global__ void scan_bsums(int *__restrict__ bsums, int nb) {
    __shared__ int sh[128];
    int tid = threadIdx.x;
    int v = (tid < nb) ? bsums[tid] : 0;
    sh[tid] = v;
    __syncthreads();
#pragma unroll
    for (int ofs = 1; ofs < 128; ofs <<= 1) {
        int t = 0;
        if (tid >= ofs) t = sh[tid - ofs];
        __syncthreads();
        sh[tid] += t;
        __syncthreads();
    }
    if (tid < nb) bsums[tid] = sh[tid] - v;  // exclusive
}

__global__ void scan_add(int *__restrict__ data, const int *__restrict__ bsums,
                         int n) {
    int gid = blockIdx.x * 512 + threadIdx.x;
    if (gid < n) data[gid] += bsums[blockIdx.x];
}

__global__ void fill_csr(const void *__restrict__ ei, int E,
                         const int *__restrict__ off, int *__restrict__ cursor,
                         int *__restrict__ csr, int N) {
    int e = blockIdx.x * blockDim.x + threadIdx.x;
    if (e < E) {
        int is64 = g_is64;
        int src = edge_at(ei, (size_t)e, is64);
        int dst = edge_at(ei, (size_t)E + e, is64);
        if ((unsigned)dst < (unsigned)N && (unsigned)src < (unsigned)N) {
            int pos = off[dst] + atomicAdd(&cursor[dst], 1);
            csr[pos] = src;
        }
    }
}

// ----------------------------- aggregation ---------------------------------
// one warp per node; VPL float4 per lane (VPL=1 -> 128 cols, VPL=2 -> 256)
template <int VPL>
__global__ void gin_agg(const float *__restrict__ x, float *__restrict__ y,
                        const int *__restrict__ off, const int *__restrict__ csr,
                        int n) {
    int warp = (blockIdx.x * blockDim.x + threadIdx.x) >> 5;
    int lane = threadIdx.x & 31;
    if (warp >= n) return;
    const int D = VPL * 128;
    float4 acc[VPL];
    const float4 *xr = (const float4 *)(x + (size_t)warp * D);
#pragma unroll
    for (int v = 0; v < VPL; v++) acc[v] = xr[lane + v * 32];  // self term (eps=0)
    int s = off[warp], e = off[warp + 1];
    for (int k = s; k < e; k++) {
        int src = csr[k];
        const float4 *sr = (const float4 *)(x + (size_t)src * D);
#pragma unroll
        for (int v = 0; v < VPL; v++) {
            float4 t = sr[lane + v * 32];
            acc[v].x += t.x; acc[v].y += t.y; acc[v].z += t.z; acc[v].w += t.w;
        }
    }
    float4 *yr = (float4 *)(y + (size_t)warp * D);
#pragma unroll
    for (int v = 0; v < VPL; v++) yr[lane + v * 32] = acc[v];
}

// ------------------------------- SGEMM -------------------------------------
// C[M,Nc] = act(A[M,K] @ B[K,Nc] + bias). Row-major. BM=BN=128, BK=16,
// 256 threads, 8x8 per thread, packed f32x2 FMAs.
template <bool RELU>
__global__ __launch_bounds__(256, 2) void sgemm_bias(
    const float *__restrict__ A, const float *__restrict__ B,
    const float *__restrict__ bias, float *__restrict__ C, int M, int K, int Nc) {
    constexpr int BM = 128, BN = 128, BK = 16;
    __shared__ __align__(16) float As[BK][BM + 4];
    __shared__ __align__(16) float Bs[BK][BN];

    int tid = threadIdx.x;
    int mBase = blockIdx.y * BM;
    int nBase = blockIdx.x * BN;
    int tcol = tid & 15;   // 0..15
    int trow = tid >> 4;   // 0..15

    int aRow = tid >> 2;          // 0..63
    int aK4 = (tid & 3) * 4;      // k start (float4 in K)
    int bK = tid >> 5;            // 0..7
    int bCol = (tid & 31) * 4;    // 0..124

    unsigned long long acc[8][4];
#pragma unroll
    for (int i = 0; i < 8; i++)
#pragma unroll
        for (int j = 0; j < 4; j++) acc[i][j] = 0ull;

    for (int k0 = 0; k0 < K; k0 += BK) {
#pragma unroll
        for (int r = 0; r < 2; r++) {
            int row = aRow + r * 64;
            int m = mBase + row;
            float4 v = make_float4(0.f, 0.f, 0.f, 0.f);
            if (m < M) v = *(const float4 *)&A[(size_t)m * K + k0 + aK4];
            As[aK4 + 0][row] = v.x;
            As[aK4 + 1][row] = v.y;
            As[aK4 + 2][row] = v.z;
            As[aK4 + 3][row] = v.w;
        }
#pragma unroll
        for (int r = 0; r < 2; r++) {
            int kk = bK + r * 8;
            *(float4 *)&Bs[kk][bCol] =
                *(const float4 *)&B[(size_t)(k0 + kk) * Nc + nBase + bCol];
        }
        __syncthreads();

#pragma unroll
        for (int dot = 0; dot < BK; dot++) {
            float4 a0 = *(const float4 *)&As[dot][trow * 8];
            float4 a1 = *(const float4 *)&As[dot][trow * 8 + 4];
            ulonglong2 b0 = *(const ulonglong2 *)&Bs[dot][tcol * 4];
            ulonglong2 b1 = *(const ulonglong2 *)&Bs[dot][64 + tcol * 4];
            float am[8] = {a0.x, a0.y, a0.z, a0.w, a1.x, a1.y, a1.z, a1.w};
#pragma unroll
            for (int i = 0; i < 8; i++) {
                unsigned long long a2 = pack2(am[i], am[i]);
                fma2(acc[i][0], a2, b0.x);
                fma2(acc[i][1], a2, b0.y);
                fma2(acc[i][2], a2, b1.x);
                fma2(acc[i][3], a2, b1.y);
            }
        }
        __syncthreads();
    }

    int n0 = nBase + tcol * 4;
    int n1 = nBase + 64 + tcol * 4;
    float4 bv0 = *(const float4 *)&bias[n0];
    float4 bv1 = *(const float4 *)&bias[n1];
#pragma unroll
    for (int i = 0; i < 8; i++) {
        int m = mBase + trow * 8 + i;
        if (m < M) {
            float2 c00 = unpack2(acc[i][0]);
            float2 c01 = unpack2(acc[i][1]);
            float2 c10 = unpack2(acc[i][2]);
            float2 c11 = unpack2(acc[i][3]);
            float4 o0 = make_float4(c00.x + bv0.x, c00.y + bv0.y,
                                    c01.x + bv0.z, c01.y + bv0.w);
            float4 o1 = make_float4(c10.x + bv1.x, c10.y + bv1.y,
                                    c11.x + bv1.z, c11.y + bv1.w);
            if (RELU) {
                o0.x = fmaxf(o0.x, 0.f); o0.y = fmaxf(o0.y, 0.f);
                o0.z = fmaxf(o0.z, 0.f); o0.w = fmaxf(o0.w, 0.f);
                o1.x = fmaxf(o1.x, 0.f); o1.y = fmaxf(o1.y, 0.f);
                o1.z = fmaxf(o1.z, 0.f); o1.w = fmaxf(o1.w, 0.f);
            }
            *(float4 *)&C[(size_t)m * Nc + n0] = o0;
            *(float4 *)&C[(size_t)m * Nc + n1] = o1;
        }
    }
}

// ------------------------------- launch ------------------------------------
extern "C" void kernel_launch(void *const *d_in, const int *in_sizes, int n_in,
                              void *d_out, int out_size) {
    const float *x   = (const float *)d_in[0];
    const float *W1a = (const float *)d_in[1];
    const float *b1a = (const float *)d_in[2];
    const float *W2a = (const float *)d_in[3];
    const float *b2a = (const float *)d_in[4];
    const float *W1b = (const float *)d_in[5];
    const float *b1b = (const float *)d_in[6];
    const float *W2b = (const float *)d_in[7];
    const float *b2b = (const float *)d_in[8];
    const void  *ei  = d_in[9];

    int N = in_sizes[0] / 128;   // 50000
    int E = in_sizes[9] / 2;     // 600000
    if (N > NMAX || E > EMAX) return;

    void *p;
    cudaGetSymbolAddress(&p, g_off);    int   *off    = (int *)p;
    cudaGetSymbolAddress(&p, g_cursor); int   *cursor = (int *)p;
    cudaGetSymbolAddress(&p, g_csr);    int   *csr    = (int *)p;
    cudaGetSymbolAddress(&p, g_bsums);  int   *bsums  = (int *)p;
    cudaGetSymbolAddress(&p, g_is64);   int   *flag   = (int *)p;
    cudaGetSymbolAddress(&p, g_h0);     float *h0     = (float *)p;
    cudaGetSymbolAddress(&p, g_bufA);   float *bufA   = (float *)p;
    cudaGetSymbolAddress(&p, g_bufB);   float *bufB   = (float *)p;

    float *out = (float *)d_out;

    // ---- edge dtype detect + CSR build ----
    detect_dtype<<<1, 32>>>((const long long *)ei, N, flag);
    zero_counts<<<(N + 256) / 256, 256>>>(off, cursor, N);
    hist_kernel<<<(E + 255) / 256, 256>>>(ei, E, off, N);
    int nScan = N + 1;
    int nb = (nScan + 511) / 512;        // 98 for N=50000
    scan_block<<<nb, 512>>>(off, bsums, nScan);
    scan_bsums<<<1, 128>>>(bsums, nb);
    scan_add<<<nb, 512>>>(off, bsums, nScan);
    fill_csr<<<(E + 255) / 256, 256>>>(ei, E, off, cursor, csr, N);

    // ---- layer 0 ----
    int aggBlocks = (N * 32 + 255) / 256;
    gin_agg<1><<<aggBlocks, 256>>>(x, h0, off, csr, N);            // h0 = x + agg0
    dim3 g256(2, (N + 127) / 128);
    sgemm_bias<true><<<g256, 256>>>(h0, W1a, b1a, bufA, N, 128, 256);   // relu
    sgemm_bias<true><<<g256, 256>>>(bufA, W2a, b2a, bufB, N, 256, 256); // + outer relu

    // ---- layer 1 ----
    gin_agg<2><<<aggBlocks, 256>>>(bufB, bufA, off, csr, N);       // g0 = h + agg1
    sgemm_bias<true><<<g256, 256>>>(bufA, W1b, b1b, bufB, N, 256, 256); // relu
    dim3 g128(1, (N + 127) / 128);
    sgemm_bias<false><<<g128, 256>>>(bufB, W2b, b2b, out, N, 256, 128); // final
}

// round 12
// speedup vs baseline: 1.3891x; 1.3891x over previous
#include <cuda_runtime.h>
#include <cuda_bf16.h>
#include <cstdint>
#include <cstddef>

// ---------------------------------------------------------------------------
// GIN 2-layer forward, bf16-split HMMA (mma.sync) GEMMs:
//   h0 = x + segsum(x);  t1 = relu(h0@W1a+b1a); h = relu(t1@W2a+b2a)
//   g0 = h + segsum(h);  t2 = relu(g0@W1b+b1b); out = t2@W2b+b2b
// GEMM: fp32 A,B split into bf16 hi+lo; D = Ah@Bh + Ah@Bl + Al@Bh (fp32 acc)
// ---------------------------------------------------------------------------

#define NMAX 50048
#define EMAX 600064

__device__ __align__(256) int   g_off[NMAX + 1];
__device__ __align__(256) int   g_cursor[NMAX];
__device__ __align__(256) int   g_csr[EMAX];
__device__ __align__(256) int   g_bsums[256];
__device__ int   g_is64;
__device__ __align__(256) float g_h0[(size_t)NMAX * 128];
__device__ __align__(256) float g_bufA[(size_t)NMAX * 256];
__device__ __align__(256) float g_bufB[(size_t)NMAX * 256];
// transposed + split weights: slot*65536, layout [N][K] bf16
__device__ __align__(256) __nv_bfloat16 g_whi[4][65536];
__device__ __align__(256) __nv_bfloat16 g_wlo[4][65536];

// ------------------------------ helpers ------------------------------------
__device__ __forceinline__ uint32_t smem_u32(const void *p) {
    uint32_t a;
    asm("{ .reg .u64 t; cvta.to.shared.u64 t, %1; cvt.u32.u64 %0, t; }"
        : "=r"(a) : "l"(p));
    return a;
}
// pack two fp32 into bf16x2 (low half = a)
__device__ __forceinline__ uint32_t cvt2bf(float a, float b) {
    uint32_t r;
    asm("cvt.rn.bf16x2.f32 %0, %1, %2;" : "=r"(r) : "f"(b), "f"(a));
    return r;
}
__device__ __forceinline__ void split2(float a, float b, uint32_t &h, uint32_t &l) {
    h = cvt2bf(a, b);
    float ha = __uint_as_float(h << 16);
    float hb = __uint_as_float(h & 0xFFFF0000u);
    l = cvt2bf(a - ha, b - hb);
}
__device__ __forceinline__ void ldmx4(uint32_t &r0, uint32_t &r1, uint32_t &r2,
                                      uint32_t &r3, uint32_t addr) {
    asm volatile("ldmatrix.sync.aligned.m8n8.x4.shared.b16 {%0,%1,%2,%3}, [%4];"
                 : "=r"(r0), "=r"(r1), "=r"(r2), "=r"(r3) : "r"(addr));
}
__device__ __forceinline__ void mma16816(float *d, const uint32_t *a,
                                         const uint32_t *b) {
    asm volatile(
        "mma.sync.aligned.m16n8k16.row.col.f32.bf16.bf16.f32 "
        "{%0,%1,%2,%3}, {%4,%5,%6,%7}, {%8,%9}, {%0,%1,%2,%3};"
        : "+f"(d[0]), "+f"(d[1]), "+f"(d[2]), "+f"(d[3])
        : "r"(a[0]), "r"(a[1]), "r"(a[2]), "r"(a[3]), "r"(b[0]), "r"(b[1]));
}

// ----------------------- edge-index dtype detection ------------------------
__global__ void detect_dtype(const long long *__restrict__ ei, int N, int *flag) {
    if (threadIdx.x == 0 && blockIdx.x == 0) {
        int ok = 1;
        for (int i = 0; i < 64; i++) {
            long long v = ei[i];
            if (v < 0 || v >= (long long)N) { ok = 0; break; }
        }
        *flag = ok;
    }
}
__device__ __forceinline__ int edge_at(const void *ei, size_t idx, int is64) {
    if (is64) return (int)((const long long *)ei)[idx];
    return ((const int *)ei)[idx];
}

// ----------------------------- CSR build -----------------------------------
__global__ void zero_counts(int *off, int *cursor, int n) {
    int i = blockIdx.x * blockDim.x + threadIdx.x;
    if (i <= n) off[i] = 0;
    if (i < n) cursor[i] = 0;
}
__global__ void hist_kernel(const void *__restrict__ ei, int E,
                            int *__restrict__ deg, int N) {
    int e = blockIdx.x * blockDim.x + threadIdx.x;
    if (e < E) {
        int dst = edge_at(ei, (size_t)E + e, g_is64);
        if ((unsigned)dst < (unsigned)N) atomicAdd(&deg[dst], 1);
    }
}
__global__ void scan_block(int *__restrict__ data, int *__restrict__ bsums, int n) {
    __shared__ int sh[512];
    int tid = threadIdx.x, gid = blockIdx.x * 512 + tid;
    int v = (gid < n) ? data[gid] : 0;
    sh[tid] = v;
    __syncthreads();
#pragma unroll
    for (int ofs = 1; ofs < 512; ofs <<= 1) {
        int t = 0;
        if (tid >= ofs) t = sh[tid - ofs];
        __syncthreads();
        sh[tid] += t;
        __syncthreads();
    }
    if (gid < n) data[gid] = sh[tid] - v;
    if (tid == 511) bsums[blockIdx.x] = sh[511];
}
__global__ void scan_bsums(int *__restrict__ bsums, int nb) {
    __shared__ int sh[128];
    int tid = threadIdx.x;
    int v = (tid < nb) ? bsums[tid] : 0;
    sh[tid] = v;
    __syncthreads();
#pragma unroll
    for (int ofs = 1; ofs < 128; ofs <<= 1) {
        int t = 0;
        if (tid >= ofs) t = sh[tid - ofs];
        __syncthreads();
        sh[tid] += t;
        __syncthreads();
    }
    if (tid < nb) bsums[tid] = sh[tid] - v;
}
__global__ void scan_add(int *__restrict__ data, const int *__restrict__ bsums, int n) {
    int gid = blockIdx.x * 512 + threadIdx.x;
    if (gid < n) data[gid] += bsums[blockIdx.x];
}
__global__ void fill_csr(const void *__restrict__ ei, int E,
                         const int *__restrict__ off, int *__restrict__ cursor,
                         int *__restrict__ csr, int N) {
    int e = blockIdx.x * blockDim.x + threadIdx.x;
    if (e < E) {
        int is64 = g_is64;
        int src = edge_at(ei, (size_t)e, is64);
        int dst = edge_at(ei, (size_t)E + e, is64);
        if ((unsigned)dst < (unsigned)N && (unsigned)src < (unsigned)N) {
            int pos = off[dst] + atomicAdd(&cursor[dst], 1);
            csr[pos] = src;
        }
    }
}

// ------------------------ weight transpose + split -------------------------
// W[K][N] fp32 -> Wt_hi/Wt_lo [N][K] bf16
__global__ void prep_w(const float *__restrict__ W, __nv_bfloat16 *__restrict__ hi,
                       __nv_bfloat16 *__restrict__ lo, int K, int N) {
    int idx = blockIdx.x * blockDim.x + threadIdx.x;
    if (idx < K * N) {
        int k = idx / N, n = idx % N;
        float x = W[idx];
        __nv_bfloat16 h = __float2bfloat16(x);
        float rem = x - __bfloat162float(h);
        hi[(size_t)n * K + k] = h;
        lo[(size_t)n * K + k] = __float2bfloat16(rem);
    }
}

// ----------------------------- aggregation ---------------------------------
template <int VPL>
__global__ void gin_agg(const float *__restrict__ x, float *__restrict__ y,
                        const int *__restrict__ off, const int *__restrict__ csr,
                        int n) {
    int warp = (blockIdx.x * blockDim.x + threadIdx.x) >> 5;
    int lane = threadIdx.x & 31;
    if (warp >= n) return;
    const int D = VPL * 128;
    float4 acc[VPL];
    const float4 *xr = (const float4 *)(x + (size_t)warp * D);
#pragma unroll
    for (int v = 0; v < VPL; v++) acc[v] = xr[lane + v * 32];
    int s = off[warp], e = off[warp + 1];
    for (int k = s; k < e; k++) {
        int src = csr[k];
        const float4 *sr = (const float4 *)(x + (size_t)src * D);
#pragma unroll
        for (int v = 0; v < VPL; v++) {
            float4 t = sr[lane + v * 32];
            acc[v].x += t.x; acc[v].y += t.y; acc[v].z += t.z; acc[v].w += t.w;
        }
    }
    float4 *yr = (float4 *)(y + (size_t)warp * D);
#pragma unroll
    for (int v = 0; v < VPL; v++) yr[lane + v * 32] = acc[v];
}

// ----------------------------- HMMA GEMM -----------------------------------
// C[M,N] = act(A[M,K] @ W + bias); W given as Bhi/Blo [N][K] bf16 (transposed).
// CTA tile 128x128, 8 warps (2m x 4n), warp tile 64x32, BK=32 chunks,
// double-buffered smem with register prefetch; split D = Ah@Bh + Ah@Bl + Al@Bh.
// Smem per buffer: Ah,Al,Bh,Bl each [128][32] bf16 padded to 40 halves/row.
#define ROWB 80           /* bytes per padded smem row (40 halves) */
#define BUFSZ (128 * ROWB)
#define SM_AH(b) ((b) * (4 * BUFSZ) + 0 * BUFSZ)
#define SM_AL(b) ((b) * (4 * BUFSZ) + 1 * BUFSZ)
#define SM_BH(b) ((b) * (4 * BUFSZ) + 2 * BUFSZ)
#define SM_BL(b) ((b) * (4 * BUFSZ) + 3 * BUFSZ)

template <int K, int N, bool RELU>
__global__ __launch_bounds__(256) void gemm_hmma(
    const float *__restrict__ A, const __nv_bfloat16 *__restrict__ Bhi,
    const __nv_bfloat16 *__restrict__ Blo, const float *__restrict__ bias,
    float *__restrict__ C, int M) {
    constexpr int NC = K / 32;
    extern __shared__ __align__(16) char ds[];
    uint32_t sb = smem_u32(ds);

    int tid = threadIdx.x, wid = tid >> 5, lane = tid & 31;
    int mBase = blockIdx.y * 128, nBase = blockIdx.x * 128;
    int mWarp = (wid >> 2) * 64;   // 0 or 64
    int nWarp = (wid & 3) * 32;    // 0,32,64,96

    // global loader mapping: thread -> (row = tid>>1, 16-elem half = tid&1)
    int lrow = tid >> 1, lhalf = tid & 1;
    int aRow = mBase + lrow;
    bool aOk = aRow < M;
    const float *aPtr = A + (size_t)(aOk ? aRow : 0) * K + lhalf * 16;
    const __nv_bfloat16 *bhPtr = Bhi + (size_t)(nBase + lrow) * K + lhalf * 16;
    const __nv_bfloat16 *blPtr = Blo + (size_t)(nBase + lrow) * K + lhalf * 16;
    uint32_t stRel = lrow * ROWB + lhalf * 32;  // byte offset in buffer

    // ldmatrix per-thread addressing: lanes 0-15 rows, 16-31 repeat w/ k+8
    int laneRow = lane & 15;
    int kOffB = (lane >> 4) * 16;  // bytes ( +8 halves )
    uint32_t aFragBase = (mWarp + laneRow) * ROWB + kOffB;
    uint32_t bFragBase = (nWarp + laneRow) * ROWB + kOffB;

    float acc[4][4][4];
#pragma unroll
    for (int i = 0; i < 4; i++)
#pragma unroll
        for (int j = 0; j < 4; j++)
#pragma unroll
            for (int q = 0; q < 4; q++) acc[i][j][q] = 0.f;

    float4 pa[4];
    uint4 pbh[2], pbl[2];

    // ---- load chunk 0 and store to buf 0 ----
    {
#pragma unroll
        for (int i = 0; i < 4; i++)
            pa[i] = aOk ? ((const float4 *)aPtr)[i] : make_float4(0, 0, 0, 0);
#pragma unroll
        for (int i = 0; i < 2; i++) {
            pbh[i] = ((const uint4 *)bhPtr)[i];
            pbl[i] = ((const uint4 *)blPtr)[i];
        }
        uint32_t h[8], l[8];
#pragma unroll
        for (int i = 0; i < 4; i++) {
            split2(pa[i].x, pa[i].y, h[2 * i], l[2 * i]);
            split2(pa[i].z, pa[i].w, h[2 * i + 1], l[2 * i + 1]);
        }
        *(uint4 *)(ds + SM_AH(0) + stRel) = make_uint4(h[0], h[1], h[2], h[3]);
        *(uint4 *)(ds + SM_AH(0) + stRel + 16) = make_uint4(h[4], h[5], h[6], h[7]);
        *(uint4 *)(ds + SM_AL(0) + stRel) = make_uint4(l[0], l[1], l[2], l[3]);
        *(uint4 *)(ds + SM_AL(0) + stRel + 16) = make_uint4(l[4], l[5], l[6], l[7]);
        *(uint4 *)(ds + SM_BH(0) + stRel) = pbh[0];
        *(uint4 *)(ds + SM_BH(0) + stRel + 16) = pbh[1];
        *(uint4 *)(ds + SM_BL(0) + stRel) = pbl[0];
        *(uint4 *)(ds + SM_BL(0) + stRel + 16) = pbl[1];
    }
    // ---- prefetch chunk 1 into regs ----
    if (NC > 1) {
#pragma unroll
        for (int i = 0; i < 4; i++)
            pa[i] = aOk ? ((const float4 *)(aPtr + 32))[i] : make_float4(0, 0, 0, 0);
#pragma unroll
        for (int i = 0; i < 2; i++) {
            pbh[i] = ((const uint4 *)(bhPtr + 32))[i];
            pbl[i] = ((const uint4 *)(blPtr + 32))[i];
        }
    }
    __syncthreads();

#pragma unroll 1
    for (int c = 0; c < NC; c++) {
        int buf = c & 1;
        // ---- compute chunk c ----
#pragma unroll
        for (int ks = 0; ks < 2; ks++) {
            uint32_t ah[4][4], al[4][4], bh[4][2], bl[4][2];
#pragma unroll
            for (int mi = 0; mi < 4; mi++)
                ldmx4(ah[mi][0], ah[mi][1], ah[mi][2], ah[mi][3],
                      sb + SM_AH(buf) + aFragBase + mi * (16 * ROWB) + ks * 32);
#pragma unroll
            for (int nj2 = 0; nj2 < 2; nj2++) {
                uint32_t r0, r1, r2, r3;
                ldmx4(r0, r1, r2, r3,
                      sb + SM_BH(buf) + bFragBase + nj2 * (16 * ROWB) + ks * 32);
                bh[nj2 * 2 + 0][0] = r0; bh[nj2 * 2 + 0][1] = r2;
                bh[nj2 * 2 + 1][0] = r1; bh[nj2 * 2 + 1][1] = r3;
            }
#pragma unroll
            for (int mi = 0; mi < 4; mi++)
                ldmx4(al[mi][0], al[mi][1], al[mi][2], al[mi][3],
                      sb + SM_AL(buf) + aFragBase + mi * (16 * ROWB) + ks * 32);
#pragma unroll
            for (int nj2 = 0; nj2 < 2; nj2++) {
                uint32_t r0, r1, r2, r3;
                ldmx4(r0, r1, r2, r3,
                      sb + SM_BL(buf) + bFragBase + nj2 * (16 * ROWB) + ks * 32);
                bl[nj2 * 2 + 0][0] = r0; bl[nj2 * 2 + 0][1] = r2;
                bl[nj2 * 2 + 1][0] = r1; bl[nj2 * 2 + 1][1] = r3;
            }
#pragma unroll
            for (int nj = 0; nj < 4; nj++)
#pragma unroll
                for (int mi = 0; mi < 4; mi++)
                    mma16816(acc[mi][nj], ah[mi], bh[nj]);
#pragma unroll
            for (int nj = 0; nj < 4; nj++)
#pragma unroll
                for (int mi = 0; mi < 4; mi++)
                    mma16816(acc[mi][nj], ah[mi], bl[nj]);
#pragma unroll
            for (int nj = 0; nj < 4; nj++)
#pragma unroll
                for (int mi = 0; mi < 4; mi++)
                    mma16816(acc[mi][nj], al[mi], bh[nj]);
        }
        // ---- store prefetched chunk c+1 into other buffer ----
        if (c + 1 < NC) {
            int nb = (c + 1) & 1;
            uint32_t h[8], l[8];
#pragma unroll
            for (int i = 0; i < 4; i++) {
                split2(pa[i].x, pa[i].y, h[2 * i], l[2 * i]);
                split2(pa[i].z, pa[i].w, h[2 * i + 1], l[2 * i + 1]);
            }
            *(uint4 *)(ds + SM_AH(nb) + stRel) = make_uint4(h[0], h[1], h[2], h[3]);
            *(uint4 *)(ds + SM_AH(nb) + stRel + 16) = make_uint4(h[4], h[5], h[6], h[7]);
            *(uint4 *)(ds + SM_AL(nb) + stRel) = make_uint4(l[0], l[1], l[2], l[3]);
            *(uint4 *)(ds + SM_AL(nb) + stRel + 16) = make_uint4(l[4], l[5], l[6], l[7]);
            *(uint4 *)(ds + SM_BH(nb) + stRel) = pbh[0];
            *(uint4 *)(ds + SM_BH(nb) + stRel + 16) = pbh[1];
            *(uint4 *)(ds + SM_BL(nb) + stRel) = pbl[0];
            *(uint4 *)(ds + SM_BL(nb) + stRel + 16) = pbl[1];
            // ---- prefetch chunk c+2 ----
            if (c + 2 < NC) {
                const float *ap = aPtr + (c + 2) * 32;
                const __nv_bfloat16 *bp = bhPtr + (c + 2) * 32;
                const __nv_bfloat16 *lp = blPtr + (c + 2) * 32;
#pragma unroll
                for (int i = 0; i < 4; i++)
                    pa[i] = aOk ? ((const float4 *)ap)[i] : make_float4(0, 0, 0, 0);
#pragma unroll
                for (int i = 0; i < 2; i++) {
                    pbh[i] = ((const uint4 *)bp)[i];
                    pbl[i] = ((const uint4 *)lp)[i];
                }
            }
        }
        __syncthreads();
    }

    // ---- epilogue: regs -> global with bias (+relu) ----
    int eRow = lane >> 2, eCol = (lane & 3) * 2;
#pragma unroll
    for (int nj = 0; nj < 4; nj++) {
        int col = nBase + nWarp + nj * 8 + eCol;
        float2 bv = *(const float2 *)&bias[col];
#pragma unroll
        for (int mi = 0; mi < 4; mi++) {
            int m0 = mBase + mWarp + mi * 16 + eRow;
            float2 v0 = make_float2(acc[mi][nj][0] + bv.x, acc[mi][nj][1] + bv.y);
            float2 v1 = make_float2(acc[mi][nj][2] + bv.x, acc[mi][nj][3] + bv.y);
            if (RELU) {
                v0.x = fmaxf(v0.x, 0.f); v0.y = fmaxf(v0.y, 0.f);
                v1.x = fmaxf(v1.x, 0.f); v1.y = fmaxf(v1.y, 0.f);
            }
            if (m0 < M) *(float2 *)&C[(size_t)m0 * N + col] = v0;
            if (m0 + 8 < M) *(float2 *)&C[(size_t)(m0 + 8) * N + col] = v1;
        }
    }
}

// ------------------------------- launch ------------------------------------
extern "C" void kernel_launch(void *const *d_in, const int *in_sizes, int n_in,
                              void *d_out, int out_size) {
    const float *x   = (const float *)d_in[0];
    const float *W1a = (const float *)d_in[1];
    const float *b1a = (const float *)d_in[2];
    const float *W2a = (const float *)d_in[3];
    const float *b2a = (const float *)d_in[4];
    const float *W1b = (const float *)d_in[5];
    const float *b1b = (const float *)d_in[6];
    const float *W2b = (const float *)d_in[7];
    const float *b2b = (const float *)d_in[8];
    const void  *ei  = d_in[9];

    int N = in_sizes[0] / 128;  // 50000
    int E = in_sizes[9] / 2;    // 600000
    if (N > NMAX || E > EMAX) return;

    void *p;
    cudaGetSymbolAddress(&p, g_off);    int *off    = (int *)p;
    cudaGetSymbolAddress(&p, g_cursor); int *cursor = (int *)p;
    cudaGetSymbolAddress(&p, g_csr);    int *csr    = (int *)p;
    cudaGetSymbolAddress(&p, g_bsums);  int *bsums  = (int *)p;
    cudaGetSymbolAddress(&p, g_is64);   int *flag   = (int *)p;
    cudaGetSymbolAddress(&p, g_h0);     float *h0   = (float *)p;
    cudaGetSymbolAddress(&p, g_bufA);   float *bufA = (float *)p;
    cudaGetSymbolAddress(&p, g_bufB);   float *bufB = (float *)p;
    cudaGetSymbolAddress(&p, g_whi);    __nv_bfloat16 *whi = (__nv_bfloat16 *)p;
    cudaGetSymbolAddress(&p, g_wlo);    __nv_bfloat16 *wlo = (__nv_bfloat16 *)p;

    float *out = (float *)d_out;

    const int SMEM_SZ = 2 * 4 * BUFSZ;  // 81920
    cudaFuncSetAttribute(gemm_hmma<128, 256, true>,
                         cudaFuncAttributeMaxDynamicSharedMemorySize, SMEM_SZ);
    cudaFuncSetAttribute(gemm_hmma<256, 256, true>,
                         cudaFuncAttributeMaxDynamicSharedMemorySize, SMEM_SZ);
    cudaFuncSetAttribute(gemm_hmma<256, 128, false>,
                         cudaFuncAttributeMaxDynamicSharedMemorySize, SMEM_SZ);

    // ---- weight prep (transpose + bf16 split) ----
    prep_w<<<(128 * 256 + 255) / 256, 256>>>(W1a, whi + 0 * 65536, wlo + 0 * 65536, 128, 256);
    prep_w<<<(256 * 256 + 255) / 256, 256>>>(W2a, whi + 1 * 65536, wlo + 1 * 65536, 256, 256);
    prep_w<<<(256 * 256 + 255) / 256, 256>>>(W1b, whi + 2 * 65536, wlo + 2 * 65536, 256, 256);
    prep_w<<<(256 * 128 + 255) / 256, 256>>>(W2b, whi + 3 * 65536, wlo + 3 * 65536, 256, 128);

    // ---- edge dtype detect + CSR build ----
    detect_dtype<<<1, 32>>>((const long long *)ei, N, flag);
    zero_counts<<<(N + 256) / 256, 256>>>(off, cursor, N);
    hist_kernel<<<(E + 255) / 256, 256>>>(ei, E, off, N);
    int nScan = N + 1;
    int nb = (nScan + 511) / 512;
    scan_block<<<nb, 512>>>(off, bsums, nScan);
    scan_bsums<<<1, 128>>>(bsums, nb);
    scan_add<<<nb, 512>>>(off, bsums, nScan);
    fill_csr<<<(E + 255) / 256, 256>>>(ei, E, off, cursor, csr, N);

    int mT = (N + 127) / 128;  // 391
    int aggBlocks = (N * 32 + 255) / 256;

    // ---- layer 0 ----
    gin_agg<1><<<aggBlocks, 256>>>(x, h0, off, csr, N);
    gemm_hmma<128, 256, true><<<dim3(2, mT), 256, SMEM_SZ>>>(
        h0, whi + 0 * 65536, wlo + 0 * 65536, b1a, bufA, N);
    gemm_hmma<256, 256, true><<<dim3(2, mT), 256, SMEM_SZ>>>(
        bufA, whi + 1 * 65536, wlo + 1 * 65536, b2a, bufB, N);

    // ---- layer 1 ----
    gin_agg<2><<<aggBlocks, 256>>>(bufB, bufA, off, csr, N);
    gemm_hmma<256, 256, true><<<dim3(2, mT), 256, SMEM_SZ>>>(
        bufA, whi + 2 * 65536, wlo + 2 * 65536, b1b, bufB, N);
    gemm_hmma<256, 128, false><<<dim3(1, mT), 256, SMEM_SZ>>>(
        bufB, whi + 3 * 65536, wlo + 3 * 65536, b2b, out, N);
}

// round 13
// speedup vs baseline: 1.5676x; 1.1285x over previous
#include <cuda_runtime.h>
#include <cuda_bf16.h>
#include <cstdint>
#include <cstddef>

// ---------------------------------------------------------------------------
// GIN 2-layer forward, bf16-split HMMA GEMMs with cp.async pipeline.
// All GEMM inputs pre-split into bf16 hi/lo by producers (agg / epilogues):
//   s0 = split(x + segsum(x));     t1 = split(relu(s0@W1a+b1a))
//   h  = relu(t1@W2a+b2a)  (fp32); s1 = split(h + segsum(h))
//   t2 = split(relu(s1@W1b+b1b));  out = t2@W2b+b2b
// D = Ah@Bh + Ah@Bl + Al@Bh (fp32 accum)
// ---------------------------------------------------------------------------

#define NMAX 50048
#define EMAX 600064

__device__ __align__(256) int   g_off[NMAX + 1];
__device__ __align__(256) int   g_cursor[NMAX];
__device__ __align__(256) int   g_csr[EMAX];
__device__ __align__(256) int   g_bsums[256];
__device__ int   g_is64;
__device__ __align__(256) float g_hbuf[(size_t)NMAX * 256];          // fp32 h
__device__ __align__(256) __nv_bfloat16 g_s0hi[(size_t)NMAX * 128];
__device__ __align__(256) __nv_bfloat16 g_s0lo[(size_t)NMAX * 128];
__device__ __align__(256) __nv_bfloat16 g_p1hi[(size_t)NMAX * 256];  // t1, t2
__device__ __align__(256) __nv_bfloat16 g_p1lo[(size_t)NMAX * 256];
__device__ __align__(256) __nv_bfloat16 g_p2hi[(size_t)NMAX * 256];  // s1
__device__ __align__(256) __nv_bfloat16 g_p2lo[(size_t)NMAX * 256];
// transposed + split weights: slot*65536, layout [N][K] bf16
__device__ __align__(256) __nv_bfloat16 g_whi[4][65536];
__device__ __align__(256) __nv_bfloat16 g_wlo[4][65536];

// ------------------------------ helpers ------------------------------------
__device__ __forceinline__ uint32_t smem_u32(const void *p) {
    uint32_t a;
    asm("{ .reg .u64 t; cvta.to.shared.u64 t, %1; cvt.u32.u64 %0, t; }"
        : "=r"(a) : "l"(p));
    return a;
}
__device__ __forceinline__ uint32_t cvt2bf(float a, float b) {  // low half = a
    uint32_t r;
    asm("cvt.rn.bf16x2.f32 %0, %1, %2;" : "=r"(r) : "f"(b), "f"(a));
    return r;
}
__device__ __forceinline__ void split2(float a, float b, uint32_t &h, uint32_t &l) {
    h = cvt2bf(a, b);
    float ha = __uint_as_float(h << 16);
    float hb = __uint_as_float(h & 0xFFFF0000u);
    l = cvt2bf(a - ha, b - hb);
}
__device__ __forceinline__ void ldmx4(uint32_t &r0, uint32_t &r1, uint32_t &r2,
                                      uint32_t &r3, uint32_t addr) {
    asm volatile("ldmatrix.sync.aligned.m8n8.x4.shared.b16 {%0,%1,%2,%3}, [%4];"
                 : "=r"(r0), "=r"(r1), "=r"(r2), "=r"(r3) : "r"(addr));
}
__device__ __forceinline__ void mma16816(float *d, const uint32_t *a,
                                         const uint32_t *b) {
    asm volatile(
        "mma.sync.aligned.m16n8k16.row.col.f32.bf16.bf16.f32 "
        "{%0,%1,%2,%3}, {%4,%5,%6,%7}, {%8,%9}, {%0,%1,%2,%3};"
        : "+f"(d[0]), "+f"(d[1]), "+f"(d[2]), "+f"(d[3])
        : "r"(a[0]), "r"(a[1]), "r"(a[2]), "r"(a[3]), "r"(b[0]), "r"(b[1]));
}
__device__ __forceinline__ void cpa16(uint32_t dst, const void *src) {
    asm volatile("cp.async.cg.shared.global [%0], [%1], 16;"
                 :: "r"(dst), "l"(src));
}
__device__ __forceinline__ void cpa_commit() {
    asm volatile("cp.async.commit_group;" ::: "memory");
}
template <int n> __device__ __forceinline__ void cpa_wait() {
    asm volatile("cp.async.wait_group %0;" :: "n"(n) : "memory");
}

// ----------------------- edge-index dtype detection ------------------------
__global__ void detect_dtype(const long long *__restrict__ ei, int N, int *flag) {
    if (threadIdx.x == 0 && blockIdx.x == 0) {
        int ok = 1;
        for (int i = 0; i < 64; i++) {
            long long v = ei[i];
            if (v < 0 || v >= (long long)N) { ok = 0; break; }
        }
        *flag = ok;
    }
}
__device__ __forceinline__ int edge_at(const void *ei, size_t idx, int is64) {
    if (is64) return (int)((const long long *)ei)[idx];
    return ((const int *)ei)[idx];
}

// ----------------------------- CSR build -----------------------------------
__global__ void zero_counts(int *off, int *cursor, int n) {
    int i = blockIdx.x * blockDim.x + threadIdx.x;
    if (i <= n) off[i] = 0;
    if (i < n) cursor[i] = 0;
}
__global__ void hist_kernel(const void *__restrict__ ei, int E,
                            int *__restrict__ deg, int N) {
    int e = blockIdx.x * blockDim.x + threadIdx.x;
    if (e < E) {
        int dst = edge_at(ei, (size_t)E + e, g_is64);
        if ((unsigned)dst < (unsigned)N) atomicAdd(&deg[dst], 1);
    }
}
__global__ void scan_block(int *__restrict__ data, int *__restrict__ bsums, int n) {
    __shared__ int sh[512];
    int tid = threadIdx.x, gid = blockIdx.x * 512 + tid;
    int v = (gid < n) ? data[gid] : 0;
    sh[tid] = v;
    __syncthreads();
#pragma unroll
    for (int ofs = 1; ofs < 512; ofs <<= 1) {
        int t = 0;
        if (tid >= ofs) t = sh[tid - ofs];
        __syncthreads();
        sh[tid] += t;
        __syncthreads();
    }
    if (gid < n) data[gid] = sh[tid] - v;
    if (tid == 511) bsums[blockIdx.x] = sh[511];
}
__global__ void scan_bsums(int *__restrict__ bsums, int nb) {
    __shared__ int sh[128];
    int tid = threadIdx.x;
    int v = (tid < nb) ? bsums[tid] : 0;
    sh[tid] = v;
    __syncthreads();
#pragma unroll
    for (int ofs = 1; ofs < 128; ofs <<= 1) {
        int t = 0;
        if (tid >= ofs) t = sh[tid - ofs];
        __syncthreads();
        sh[tid] += t;
        __syncthreads();
    }
    if (tid < nb) bsums[tid] = sh[tid] - v;
}
__global__ void scan_add(int *__restrict__ data, const int *__restrict__ bsums, int n) {
    int gid = blockIdx.x * 512 + threadIdx.x;
    if (gid < n) data[gid] += bsums[blockIdx.x];
}
__global__ void fill_csr(const void *__restrict__ ei, int E,
                         const int *__restrict__ off, int *__restrict__ cursor,
                         int *__restrict__ csr, int N) {
    int e = blockIdx.x * blockDim.x + threadIdx.x;
    if (e < E) {
        int is64 = g_is64;
        int src = edge_at(ei, (size_t)e, is64);
        int dst = edge_at(ei, (size_t)E + e, is64);
        if ((unsigned)dst < (unsigned)N && (unsigned)src < (unsigned)N) {
            int pos = off[dst] + atomicAdd(&cursor[dst], 1);
            csr[pos] = src;
        }
    }
}

// ------------------------ weight transpose + split -------------------------
// All 4 weight matrices in ONE launch. W[K][N] fp32 -> [N][K] bf16 hi/lo.
__global__ void prep_w_all(const float *W1a, const float *W2a, const float *W1b,
                           const float *W2b, __nv_bfloat16 *hi, __nv_bfloat16 *lo) {
    int idx = blockIdx.x * blockDim.x + threadIdx.x;  // 0 .. 196607
    const float *W;
    int K, N, slot, loc;
    if (idx < 32768)       { W = W1a; K = 128; N = 256; slot = 0; loc = idx; }
    else if (idx < 98304)  { W = W2a; K = 256; N = 256; slot = 1; loc = idx - 32768; }
    else if (idx < 163840) { W = W1b; K = 256; N = 256; slot = 2; loc = idx - 98304; }
    else if (idx < 196608) { W = W2b; K = 256; N = 128; slot = 3; loc = idx - 163840; }
    else return;
    int k = loc / N, n = loc % N;
    float x = W[loc];
    __nv_bfloat16 h = __float2bfloat16(x);
    float rem = x - __bfloat162float(h);
    hi[slot * 65536 + (size_t)n * K + k] = h;
    lo[slot * 65536 + (size_t)n * K + k] = __float2bfloat16(rem);
}

// ------------------- aggregation (fp32 in, split bf16 out) -----------------
template <int VPL>
__global__ void gin_agg_split(const float *__restrict__ x,
                              __nv_bfloat16 *__restrict__ yhi,
                              __nv_bfloat16 *__restrict__ ylo,
                              const int *__restrict__ off,
                              const int *__restrict__ csr, int n) {
    int warp = (blockIdx.x * blockDim.x + threadIdx.x) >> 5;
    int lane = threadIdx.x & 31;
    if (warp >= n) return;
    const int D = VPL * 128;
    float4 acc[VPL];
    const float4 *xr = (const float4 *)(x + (size_t)warp * D);
#pragma unroll
    for (int v = 0; v < VPL; v++) acc[v] = xr[lane + v * 32];  // self (eps=0)
    int s = off[warp], e = off[warp + 1];
    for (int k = s; k < e; k++) {
        int src = csr[k];
        const float4 *sr = (const float4 *)(x + (size_t)src * D);
#pragma unroll
        for (int v = 0; v < VPL; v++) {
            float4 t = sr[lane + v * 32];
            acc[v].x += t.x; acc[v].y += t.y; acc[v].z += t.z; acc[v].w += t.w;
        }
    }
#pragma unroll
    for (int v = 0; v < VPL; v++) {
        uint32_t h0, l0, h1, l1;
        split2(acc[v].x, acc[v].y, h0, l0);
        split2(acc[v].z, acc[v].w, h1, l1);
        size_t o = (size_t)warp * D + (lane + v * 32) * 4;
        *(uint2 *)&yhi[o] = make_uint2(h0, h1);
        *(uint2 *)&ylo[o] = make_uint2(l0, l1);
    }
}

// ----------------------------- HMMA GEMM -----------------------------------
// C = act(A @ W + bias); A as Ahi/Alo [M][K] bf16, W as Bhi/Blo [N][K] bf16.
// CTA tile 128x128, 8 warps (2m x 4n), BK=32, cp.async 2-stage pipeline.
#define ROWB 80
#define BUFB (128 * ROWB)      /* 10240 bytes per operand buffer */
#define STAGEB (4 * BUFB)      /* 40960 bytes per stage */

template <int K, int N, bool RELU, bool SPLITOUT>
__global__ __launch_bounds__(256, 2) void gemm_hmma(
    const __nv_bfloat16 *__restrict__ Ahi, const __nv_bfloat16 *__restrict__ Alo,
    const __nv_bfloat16 *__restrict__ Bhi, const __nv_bfloat16 *__restrict__ Blo,
    const float *__restrict__ bias, float *__restrict__ Cf,
    __nv_bfloat16 *__restrict__ Chi, __nv_bfloat16 *__restrict__ Clo, int M) {
    constexpr int NC = K / 32;
    extern __shared__ __align__(16) char ds[];
    uint32_t sb = smem_u32(ds);

    int tid = threadIdx.x, wid = tid >> 5, lane = tid & 31;
    int mBase = blockIdx.y * 128, nBase = blockIdx.x * 128;
    int mWarp = (wid >> 2) * 64;
    int nWarp = (wid & 3) * 32;

    // cp.async loader mapping: group g = operand, 64 threads per operand
    int g = tid >> 6, t = tid & 63;
    const __nv_bfloat16 *gp = (g == 0) ? Ahi : (g == 1) ? Alo : (g == 2) ? Bhi : Blo;
    int rowBase = (g < 2) ? mBase : nBase;
    uint32_t dstBase = sb + g * BUFB;

    // ldmatrix addressing
    int laneRow = lane & 15;
    int kOffB = (lane >> 4) * 16;
    uint32_t aFragBase = sb + (mWarp + laneRow) * ROWB + kOffB;          // +stage, +AH/AL
    uint32_t bFragBase = sb + (nWarp + laneRow) * ROWB + kOffB + 2 * BUFB;

    float acc[4][4][4];
#pragma unroll
    for (int i = 0; i < 4; i++)
#pragma unroll
        for (int j = 0; j < 4; j++)
#pragma unroll
            for (int q = 0; q < 4; q++) acc[i][j][q] = 0.f;

    // ---- issue one chunk's cp.asyncs for this thread ----
    auto issue = [&](int chunk, int stage) {
#pragma unroll
        for (int i = 0; i < 8; i++) {
            int idx = i * 64 + t;
            int row = idx >> 2, c16 = idx & 3;
            int r = rowBase + row;
            if (g < 2 && r >= M) r = M - 1;  // clamp (rows >= M never stored)
            const void *src = gp + (size_t)r * K + chunk * 32 + c16 * 8;
            cpa16(dstBase + stage * STAGEB + row * ROWB + c16 * 16, src);
        }
        cpa_commit();
    };

    issue(0, 0);
    if (NC > 1) issue(1, 1);
    cpa_wait<(NC > 1) ? 1 : 0>();
    __syncthreads();

#pragma unroll 1
    for (int c = 0; c < NC; c++) {
        int buf = c & 1;
        uint32_t stage = buf * STAGEB;
#pragma unroll
        for (int ks = 0; ks < 2; ks++) {
            uint32_t ah[4][4], bh[4][2], bx[4][2], al4[4];
            // term 1: Ah @ Bh
#pragma unroll
            for (int mi = 0; mi < 4; mi++)
                ldmx4(ah[mi][0], ah[mi][1], ah[mi][2], ah[mi][3],
                      aFragBase + stage + mi * (16 * ROWB) + ks * 32);
#pragma unroll
            for (int nj2 = 0; nj2 < 2; nj2++) {
                uint32_t r0, r1, r2, r3;
                ldmx4(r0, r1, r2, r3,
                      bFragBase + stage + nj2 * (16 * ROWB) + ks * 32);
                bh[nj2 * 2 + 0][0] = r0; bh[nj2 * 2 + 0][1] = r2;
                bh[nj2 * 2 + 1][0] = r1; bh[nj2 * 2 + 1][1] = r3;
            }
#pragma unroll
            for (int nj = 0; nj < 4; nj++)
#pragma unroll
                for (int mi = 0; mi < 4; mi++)
                    mma16816(acc[mi][nj], ah[mi], bh[nj]);
            // term 2: Ah @ Bl
#pragma unroll
            for (int nj2 = 0; nj2 < 2; nj2++) {
                uint32_t r0, r1, r2, r3;
                ldmx4(r0, r1, r2, r3,
                      bFragBase + stage + BUFB + nj2 * (16 * ROWB) + ks * 32);
                bx[nj2 * 2 + 0][0] = r0; bx[nj2 * 2 + 0][1] = r2;
                bx[nj2 * 2 + 1][0] = r1; bx[nj2 * 2 + 1][1] = r3;
            }
#pragma unroll
            for (int nj = 0; nj < 4; nj++)
#pragma unroll
                for (int mi = 0; mi < 4; mi++)
                    mma16816(acc[mi][nj], ah[mi], bx[nj]);
            // term 3: Al @ Bh  (reuse ah regs for al, one mi at a time)
#pragma unroll
            for (int mi = 0; mi < 4; mi++) {
                ldmx4(al4[0], al4[1], al4[2], al4[3],
                      aFragBase + stage + BUFB + mi * (16 * ROWB) + ks * 32);
#pragma unroll
                for (int nj = 0; nj < 4; nj++)
                    mma16816(acc[mi][nj], al4, bh[nj]);
            }
        }
        __syncthreads();
        if (c + 2 < NC) {
            issue(c + 2, buf);
            cpa_wait<1>();
        } else if (c + 1 < NC) {
            cpa_wait<0>();
        }
        __syncthreads();
    }

    // ---- epilogue ----
    int eRow = lane >> 2, eCol = (lane & 3) * 2;
#pragma unroll
    for (int nj = 0; nj < 4; nj++) {
        int col = nBase + nWarp + nj * 8 + eCol;
        float2 bv = *(const float2 *)&bias[col];
#pragma unroll
        for (int mi = 0; mi < 4; mi++) {
            int m0 = mBase + mWarp + mi * 16 + eRow;
            float2 v0 = make_float2(acc[mi][nj][0] + bv.x, acc[mi][nj][1] + bv.y);
            float2 v1 = make_float2(acc[mi][nj][2] + bv.x, acc[mi][nj][3] + bv.y);
            if (RELU) {
                v0.x = fmaxf(v0.x, 0.f); v0.y = fmaxf(v0.y, 0.f);
                v1.x = fmaxf(v1.x, 0.f); v1.y = fmaxf(v1.y, 0.f);
            }
            if (SPLITOUT) {
                uint32_t h, l;
                if (m0 < M) {
                    split2(v0.x, v0.y, h, l);
                    *(uint32_t *)&Chi[(size_t)m0 * N + col] = h;
                    *(uint32_t *)&Clo[(size_t)m0 * N + col] = l;
                }
                if (m0 + 8 < M) {
                    split2(v1.x, v1.y, h, l);
                    *(uint32_t *)&Chi[(size_t)(m0 + 8) * N + col] = h;
                    *(uint32_t *)&Clo[(size_t)(m0 + 8) * N + col] = l;
                }
            } else {
                if (m0 < M) *(float2 *)&Cf[(size_t)m0 * N + col] = v0;
                if (m0 + 8 < M) *(float2 *)&Cf[(size_t)(m0 + 8) * N + col] = v1;
            }
        }
    }
}

// ------------------------------- launch ------------------------------------
extern "C" void kernel_launch(void *const *d_in, const int *in_sizes, int n_in,
                              void *d_out, int out_size) {
    const float *x   = (const float *)d_in[0];
    const float *W1a = (const float *)d_in[1];
    const float *b1a = (const float *)d_in[2];
    const float *W2a = (const float *)d_in[3];
    const float *b2a = (const float *)d_in[4];
    const float *W1b = (const float *)d_in[5];
    const float *b1b = (const float *)d_in[6];
    const float *W2b = (const float *)d_in[7];
    const float *b2b = (const float *)d_in[8];
    const void  *ei  = d_in[9];

    int N = in_sizes[0] / 128;  // 50000
    int E = in_sizes[9] / 2;    // 600000
    if (N > NMAX || E > EMAX) return;

    void *p;
    cudaGetSymbolAddress(&p, g_off);    int *off    = (int *)p;
    cudaGetSymbolAddress(&p, g_cursor); int *cursor = (int *)p;
    cudaGetSymbolAddress(&p, g_csr);    int *csr    = (int *)p;
    cudaGetSymbolAddress(&p, g_bsums);  int *bsums  = (int *)p;
    cudaGetSymbolAddress(&p, g_is64);   int *flag   = (int *)p;
    cudaGetSymbolAddress(&p, g_hbuf);   float *hbuf = (float *)p;
    cudaGetSymbolAddress(&p, g_s0hi);   __nv_bfloat16 *s0hi = (__nv_bfloat16 *)p;
    cudaGetSymbolAddress(&p, g_s0lo);   __nv_bfloat16 *s0lo = (__nv_bfloat16 *)p;
    cudaGetSymbolAddress(&p, g_p1hi);   __nv_bfloat16 *p1hi = (__nv_bfloat16 *)p;
    cudaGetSymbolAddress(&p, g_p1lo);   __nv_bfloat16 *p1lo = (__nv_bfloat16 *)p;
    cudaGetSymbolAddress(&p, g_p2hi);   __nv_bfloat16 *p2hi = (__nv_bfloat16 *)p;
    cudaGetSymbolAddress(&p, g_p2lo);   __nv_bfloat16 *p2lo = (__nv_bfloat16 *)p;
    cudaGetSymbolAddress(&p, g_whi);    __nv_bfloat16 *whi = (__nv_bfloat16 *)p;
    cudaGetSymbolAddress(&p, g_wlo);    __nv_bfloat16 *wlo = (__nv_bfloat16 *)p;

    float *out = (float *)d_out;

    const int SMEM_SZ = 2 * STAGEB;  // 81920
    cudaFuncSetAttribute(gemm_hmma<128, 256, true, true>,
                         cudaFuncAttributeMaxDynamicSharedMemorySize, SMEM_SZ);
    cudaFuncSetAttribute(gemm_hmma<256, 256, true, false>,
                         cudaFuncAttributeMaxDynamicSharedMemorySize, SMEM_SZ);
    cudaFuncSetAttribute(gemm_hmma<256, 256, true, true>,
                         cudaFuncAttributeMaxDynamicSharedMemorySize, SMEM_SZ);
    cudaFuncSetAttribute(gemm_hmma<256, 128, false, false>,
                         cudaFuncAttributeMaxDynamicSharedMemorySize, SMEM_SZ);

    // ---- weight prep (single launch) ----
    prep_w_all<<<(196608 + 255) / 256, 256>>>(W1a, W2a, W1b, W2b, whi, wlo);

    // ---- edge dtype detect + CSR build ----
    detect_dtype<<<1, 32>>>((const long long *)ei, N, flag);
    zero_counts<<<(N + 256) / 256, 256>>>(off, cursor, N);
    hist_kernel<<<(E + 255) / 256, 256>>>(ei, E, off, N);
    int nScan = N + 1;
    int nb = (nScan + 511) / 512;
    scan_block<<<nb, 512>>>(off, bsums, nScan);
    scan_bsums<<<1, 128>>>(bsums, nb);
    scan_add<<<nb, 512>>>(off, bsums, nScan);
    fill_csr<<<(E + 255) / 256, 256>>>(ei, E, off, cursor, csr, N);

    int mT = (N + 127) / 128;  // 391
    int aggBlocks = (N * 32 + 255) / 256;

    // ---- layer 0 ----
    gin_agg_split<1><<<aggBlocks, 256>>>(x, s0hi, s0lo, off, csr, N);
    gemm_hmma<128, 256, true, true><<<dim3(2, mT), 256, SMEM_SZ>>>(
        s0hi, s0lo, whi + 0 * 65536, wlo + 0 * 65536, b1a,
        nullptr, p1hi, p1lo, N);
    gemm_hmma<256, 256, true, false><<<dim3(2, mT), 256, SMEM_SZ>>>(
        p1hi, p1lo, whi + 1 * 65536, wlo + 1 * 65536, b2a,
        hbuf, nullptr, nullptr, N);

    // ---- layer 1 ----
    gin_agg_split<2><<<aggBlocks, 256>>>(hbuf, p2hi, p2lo, off, csr, N);
    gemm_hmma<256, 256, true, true><<<dim3(2, mT), 256, SMEM_SZ>>>(
        p2hi, p2lo, whi + 2 * 65536, wlo + 2 * 65536, b1b,
        nullptr, p1hi, p1lo, N);
    gemm_hmma<256, 128, false, false><<<dim3(1, mT), 256, SMEM_SZ>>>(
        p1hi, p1lo, whi + 3 * 65536, wlo + 3 * 65536, b2b,
        out, nullptr, nullptr, N);
}